// round 16
// baseline (speedup 1.0000x reference)
#include <cuda_runtime.h>
#include <math.h>

// Problem constants (fixed shapes from the reference)
#define N_ENT   14541
#define N_REL   237
#define M_EDGES 272115
#define D       256
#define BS      16
#define NT      4                        // entities per warp-tile
#define OUT_ELEMS (N_ENT * BS)

#define NBLK     296                     // 2 blocks/SM: co-residency guaranteed
#define THREADS  128                     // 4 warps/block
#define GTHREADS (NBLK * THREADS)        // 37888
#define GWARPS   (GTHREADS / 32)         // 1184
#define TILES    ((N_ENT + NT - 1) / NT) // 3636
#define SLAB     (GTHREADS * 4)          // 151552 edges per phase-2 slab

// Scratch (static device arrays; no runtime allocation)
__device__ float        g_sig[N_ENT * BS];
__device__ int          g_bar_count = 0;
__device__ volatile int g_bar_sense = 0;

// ---------------------------------------------------------------------------
// Single persistent kernel:
//   phase 1: dist — sig[n][b] = sigmoid(12 - sum_d |rel|*|emb - all_emb|),
//            self-masked to 0; warps loop over NT=4-entity tiles.
//   barrier: sense-reversing grid barrier (296 co-resident blocks).
//   phase 2: edge — filter by relation bitmask (smem), gather sig[head][b],
//            atomic scatter-add onto out[b][tail]. 2 int4 slabs/thread (MLP=2).
// ---------------------------------------------------------------------------
__global__ void __launch_bounds__(THREADS) fused_kernel(
    const float* __restrict__ emb,
    const float* __restrict__ all_emb,
    const float* __restrict__ tail_r,
    const int*   __restrict__ source_idx,
    const int*   __restrict__ relation_ids,
    const int*   __restrict__ heads,
    const int*   __restrict__ tails,
    const int*   __restrict__ rels,
    float*       __restrict__ out)
{
    __shared__ float    es[BS * D];     // emb[b][d]
    __shared__ float    rs[BS * D];     // |tail_r[relation_ids[b]][d]|
    __shared__ int      s_rel[BS];
    __shared__ int      s_src[BS];
    __shared__ unsigned s_mask[N_REL];  // relation -> batch bitmask

    const int tid  = threadIdx.x;
    const int lane = tid & 31;
    const int gtid = blockIdx.x * THREADS + tid;

    // Zero the output buffer (930 KB over 37888 threads, coalesced strided).
    for (int i = gtid; i < OUT_ELEMS; i += GTHREADS) out[i] = 0.f;

    if (tid < BS) {
        s_rel[tid] = relation_ids[tid];
        s_src[tid] = source_idx[tid];
    }
    __syncthreads();

    if (tid < N_REL) {
        unsigned m = 0;
        #pragma unroll
        for (int b = 0; b < BS; b++)
            m |= (s_rel[b] == tid) ? (1u << b) : 0u;
        s_mask[tid] = m;
    }
    if (tid + THREADS < N_REL) {        // cover 237 entries with 128 threads
        const int r2 = tid + THREADS;
        unsigned m = 0;
        #pragma unroll
        for (int b = 0; b < BS; b++)
            m |= (s_rel[b] == r2) ? (1u << b) : 0u;
        s_mask[r2] = m;
    }
    for (int i = tid; i < BS * D; i += THREADS) {
        int b = i >> 8;          // i / D
        int d = i & (D - 1);     // i % D
        es[i] = emb[i];
        rs[i] = fabsf(tail_r[s_rel[b] * D + d]);
    }
    __syncthreads();

    // ---- Phase 1: distance tiles (proven scalar R3 body, looped) ----
    const int gwarp = blockIdx.x * (THREADS / 32) + (tid >> 5);
    const float4* es4 = (const float4*)es;
    const float4* rs4 = (const float4*)rs;

    #pragma unroll 1
    for (int tile = gwarp; tile < TILES; tile += GWARPS) {
        const int n0 = tile * NT;

        float4 xl[NT], xh[NT];
        #pragma unroll
        for (int n = 0; n < NT; n++) {
            int nn = n0 + n; if (nn >= N_ENT) nn = N_ENT - 1;
            const float4* row = (const float4*)(all_emb + nn * D);
            xl[n] = row[lane];
            xh[n] = row[32 + lane];
        }

        float acc[NT * BS];
        #pragma unroll
        for (int i = 0; i < NT * BS; i++) acc[i] = 0.f;

        #pragma unroll
        for (int b = 0; b < BS; b++) {
            float4 e0 = es4[b * 64 + lane];
            float4 e1 = es4[b * 64 + 32 + lane];
            float4 r0 = rs4[b * 64 + lane];
            float4 r1 = rs4[b * 64 + 32 + lane];
            #pragma unroll
            for (int n = 0; n < NT; n++) {
                float s = acc[n * BS + b];
                s += r0.x * fabsf(e0.x - xl[n].x);
                s += r0.y * fabsf(e0.y - xl[n].y);
                s += r0.z * fabsf(e0.z - xl[n].z);
                s += r0.w * fabsf(e0.w - xl[n].w);
                s += r1.x * fabsf(e1.x - xh[n].x);
                s += r1.y * fabsf(e1.y - xh[n].y);
                s += r1.z * fabsf(e1.z - xh[n].z);
                s += r1.w * fabsf(e1.w - xh[n].w);
                acc[n * BS + b] = s;
            }
        }

        // Value-splitting butterfly: 64 partials -> 62 shuffles; lane L ends
        // with flat sums 2L and 2L+1, where flat = n_local*16 + b.
        #pragma unroll
        for (int step = 0; step < 5; step++) {
            const int mask = 16 >> step;
            const int V    = 64 >> step;
            const bool hi  = (lane & mask) != 0;
            #pragma unroll
            for (int i = 0; i < V / 2; i++) {
                float send = hi ? acc[i]         : acc[i + V / 2];
                float keep = hi ? acc[i + V / 2] : acc[i];
                float other = __shfl_xor_sync(0xffffffffu, send, mask);
                acc[i] = keep + other;
            }
        }

        const int f  = 2 * lane;
        const int nn = n0 + (f >> 4);
        const int b  = f & 15;
        if (nn < N_ENT) {
            float s0 = 1.0f / (1.0f + __expf(acc[0] - 12.0f));
            float s1 = 1.0f / (1.0f + __expf(acc[1] - 12.0f));
            if (nn == s_src[b])     s0 = 0.0f;
            if (nn == s_src[b + 1]) s1 = 0.0f;
            *(float2*)(g_sig + nn * BS + b) = make_float2(s0, s1);
        }
    }

    // ---- Grid barrier (sense-reversing; validated in R9; replay-safe) ----
    __syncthreads();
    if (tid == 0) {
        const int s = g_bar_sense;
        __threadfence();                       // publish sig + out zeroing
        if (atomicAdd(&g_bar_count, 1) == NBLK - 1) {
            g_bar_count = 0;
            __threadfence();
            g_bar_sense = s ^ 1;               // release
        } else {
            while (g_bar_sense == s) {}
        }
        __threadfence();
    }
    __syncthreads();

    // ---- Phase 2: edge filter + scatter, 2 independent int4 slabs ----
    {
        const int base0 = gtid * 4;            // always < SLAB <= M_EDGES
        const int base1 = base0 + SLAB;

        int4 ra = *(const int4*)(rels + base0);            // slab 0: full
        int4 rb; bool full1 = (base1 + 4 <= M_EDGES);
        if (full1) rb = *(const int4*)(rels + base1);

        unsigned ma[4] = { s_mask[ra.x], s_mask[ra.y], s_mask[ra.z], s_mask[ra.w] };
        unsigned any_a = ma[0] | ma[1] | ma[2] | ma[3];
        if (any_a) {
            int4 ha = *(const int4*)(heads + base0);
            int4 ta = *(const int4*)(tails + base0);
            const int h[4] = { ha.x, ha.y, ha.z, ha.w };
            const int t[4] = { ta.x, ta.y, ta.z, ta.w };
            #pragma unroll
            for (int k = 0; k < 4; k++) {
                unsigned m = ma[k];
                while (m) {
                    int b = __ffs(m) - 1;
                    m &= m - 1;
                    atomicAdd(out + b * N_ENT + t[k], g_sig[h[k] * BS + b]);
                }
            }
        }

        if (full1) {
            unsigned mb[4] = { s_mask[rb.x], s_mask[rb.y], s_mask[rb.z], s_mask[rb.w] };
            unsigned any_b = mb[0] | mb[1] | mb[2] | mb[3];
            if (any_b) {
                int4 hb = *(const int4*)(heads + base1);
                int4 tb = *(const int4*)(tails + base1);
                const int h[4] = { hb.x, hb.y, hb.z, hb.w };
                const int t[4] = { tb.x, tb.y, tb.z, tb.w };
                #pragma unroll
                for (int k = 0; k < 4; k++) {
                    unsigned m = mb[k];
                    while (m) {
                        int b = __ffs(m) - 1;
                        m &= m - 1;
                        atomicAdd(out + b * N_ENT + t[k], g_sig[h[k] * BS + b]);
                    }
                }
            }
        } else if (base1 < M_EDGES) {
            for (int k = base1; k < M_EDGES; k++) {
                unsigned m = s_mask[rels[k]];
                while (m) {
                    int b = __ffs(m) - 1;
                    m &= m - 1;
                    atomicAdd(out + b * N_ENT + tails[k], g_sig[heads[k] * BS + b]);
                }
            }
        }
    }
}

// ---------------------------------------------------------------------------
extern "C" void kernel_launch(void* const* d_in, const int* in_sizes, int n_in,
                              void* d_out, int out_size) {
    const float* emb          = (const float*)d_in[0];
    const float* all_emb      = (const float*)d_in[1];
    const float* tail_r       = (const float*)d_in[2];
    const int*   source_idx   = (const int*)  d_in[3];
    const int*   relation_ids = (const int*)  d_in[4];
    const int*   heads        = (const int*)  d_in[5];
    const int*   tails        = (const int*)  d_in[6];
    const int*   edge_rels    = (const int*)  d_in[7];
    float*       out          = (float*)d_out;

    fused_kernel<<<NBLK, THREADS>>>(emb, all_emb, tail_r, source_idx,
                                    relation_ids, heads, tails, edge_rels, out);
}

// round 17
// speedup vs baseline: 2.3872x; 2.3872x over previous
#include <cuda_runtime.h>
#include <math.h>

// Problem constants (fixed shapes from the reference)
#define N_ENT   14541
#define N_REL   237
#define M_EDGES 272115
#define D       256
#define BS      16
#define NT      4                       // entities per warp tile
#define OUT_ELEMS (N_ENT * BS)

// Scratch (static device arrays; no runtime allocation)
__device__ float    g_sig[N_ENT * BS];
__device__ unsigned g_relmask[N_REL];

// ---------------------------------------------------------------------------
// dist: sig[n][b] = sigmoid(12 - sum_d |rel[b,d]| * |emb[b,d] - all_emb[n,d]|)
//       with sig[source_idx[b]][b] = 0 (sigmoid(12-1e8) == 0 in fp32).
// One warp handles NT=4 entities; lane owns d in {4L..4L+3} u {128+4L..128+4L+3}.
// (R3 formulation — best measured dist.) Side jobs: zero `out`; block 0
// builds the relation->batch bitmask consumed by the edge kernel.
// ---------------------------------------------------------------------------
__global__ void __launch_bounds__(256) dist_kernel(
    const float* __restrict__ emb,
    const float* __restrict__ all_emb,
    const float* __restrict__ tail_r,
    const int*   __restrict__ source_idx,
    const int*   __restrict__ relation_ids,
    float*       __restrict__ out)
{
    __shared__ float es[BS * D];   // emb[b][d]
    __shared__ float rs[BS * D];   // |tail_r[relation_ids[b]][d]|
    __shared__ int   s_src[BS];

    const int tid  = threadIdx.x;
    const int lane = tid & 31;

    // Zero the output buffer (930 KB over 455 blocks, float2/thread).
    {
        const int i0 = (blockIdx.x * 256 + tid) * 2;
        if (i0 + 2 <= OUT_ELEMS)
            *(float2*)(out + i0) = make_float2(0.f, 0.f);
        else if (i0 < OUT_ELEMS)
            out[i0] = 0.f;
    }

    // Block 0: relation->batch bitmask for the edge kernel.
    if (blockIdx.x == 0 && tid < N_REL) {
        unsigned m = 0;
        #pragma unroll
        for (int b = 0; b < BS; b++)
            m |= (relation_ids[b] == tid) ? (1u << b) : 0u;
        g_relmask[tid] = m;
    }

    if (tid < BS) s_src[tid] = source_idx[tid];
    for (int i = tid; i < BS * D; i += 256) {
        int b = i >> 8;          // i / D
        int d = i & (D - 1);     // i % D
        es[i] = emb[i];
        rs[i] = fabsf(tail_r[relation_ids[b] * D + d]);
    }
    __syncthreads();

    const int warp = blockIdx.x * 8 + (tid >> 5);
    const int n0   = warp * NT;
    if (n0 >= N_ENT) return;
    const bool full_tile = (n0 + NT <= N_ENT);

    // Preload all_emb rows for this tile (coalesced LDG.128)
    float4 xl[NT], xh[NT];
    if (full_tile) {
        #pragma unroll
        for (int n = 0; n < NT; n++) {
            const float4* row = (const float4*)(all_emb + (n0 + n) * D);
            xl[n] = row[lane];
            xh[n] = row[32 + lane];
        }
    } else {
        #pragma unroll
        for (int n = 0; n < NT; n++) {
            int nn = n0 + n; if (nn >= N_ENT) nn = N_ENT - 1;
            const float4* row = (const float4*)(all_emb + nn * D);
            xl[n] = row[lane];
            xh[n] = row[32 + lane];
        }
    }

    float acc[NT * BS];
    #pragma unroll
    for (int i = 0; i < NT * BS; i++) acc[i] = 0.f;

    const float4* es4 = (const float4*)es;
    const float4* rs4 = (const float4*)rs;

    #pragma unroll
    for (int b = 0; b < BS; b++) {
        float4 e0 = es4[b * 64 + lane];
        float4 e1 = es4[b * 64 + 32 + lane];
        float4 r0 = rs4[b * 64 + lane];
        float4 r1 = rs4[b * 64 + 32 + lane];
        #pragma unroll
        for (int n = 0; n < NT; n++) {
            float s = acc[n * BS + b];
            s += r0.x * fabsf(e0.x - xl[n].x);
            s += r0.y * fabsf(e0.y - xl[n].y);
            s += r0.z * fabsf(e0.z - xl[n].z);
            s += r0.w * fabsf(e0.w - xl[n].w);
            s += r1.x * fabsf(e1.x - xh[n].x);
            s += r1.y * fabsf(e1.y - xh[n].y);
            s += r1.z * fabsf(e1.z - xh[n].z);
            s += r1.w * fabsf(e1.w - xh[n].w);
            acc[n * BS + b] = s;
        }
    }

    // Value-splitting butterfly: 64 partials -> 62 shuffles; lane L ends
    // with flat sums 2L and 2L+1, where flat = n_local*16 + b.
    #pragma unroll
    for (int step = 0; step < 5; step++) {
        const int mask = 16 >> step;
        const int V    = 64 >> step;
        const bool hi  = (lane & mask) != 0;
        #pragma unroll
        for (int i = 0; i < V / 2; i++) {
            float send = hi ? acc[i]         : acc[i + V / 2];
            float keep = hi ? acc[i + V / 2] : acc[i];
            float other = __shfl_xor_sync(0xffffffffu, send, mask);
            acc[i] = keep + other;
        }
    }

    // Epilogue: mask + sigmoid, coalesced float2 store
    const int f  = 2 * lane;
    const int nn = n0 + (f >> 4);
    const int b  = f & 15;
    if (nn < N_ENT) {
        float s0 = 1.0f / (1.0f + __expf(acc[0] - 12.0f));
        float s1 = 1.0f / (1.0f + __expf(acc[1] - 12.0f));
        if (nn == s_src[b])     s0 = 0.0f;
        if (nn == s_src[b + 1]) s1 = 0.0f;
        *(float2*)(g_sig + nn * BS + b) = make_float2(s0, s1);
    }
}

// ---------------------------------------------------------------------------
// edge: one edge per thread (measured 6.0-6.1us). Coalesced rel load ->
// L1-resident bitmask probe; ~93% of threads exit immediately. Survivors
// gather sig[head][b] and atomically scatter-add onto out[b][tail].
// ---------------------------------------------------------------------------
__global__ void __launch_bounds__(256, 8) edge_kernel(
    const int* __restrict__ heads,
    const int* __restrict__ tails,
    const int* __restrict__ rels,
    float*     __restrict__ out)
{
    const int i = blockIdx.x * 256 + threadIdx.x;
    if (i >= M_EDGES) return;

    const int r = __ldg(rels + i);
    unsigned m = g_relmask[r];
    if (!m) return;

    const int h = __ldg(heads + i);
    const int t = __ldg(tails + i);
    do {
        int b = __ffs(m) - 1;
        m &= m - 1;
        atomicAdd(out + b * N_ENT + t, g_sig[h * BS + b]);
    } while (m);
}

// ---------------------------------------------------------------------------
extern "C" void kernel_launch(void* const* d_in, const int* in_sizes, int n_in,
                              void* d_out, int out_size) {
    const float* emb          = (const float*)d_in[0];
    const float* all_emb      = (const float*)d_in[1];
    const float* tail_r       = (const float*)d_in[2];
    const int*   source_idx   = (const int*)  d_in[3];
    const int*   relation_ids = (const int*)  d_in[4];
    const int*   heads        = (const int*)  d_in[5];
    const int*   tails        = (const int*)  d_in[6];
    const int*   edge_rels    = (const int*)  d_in[7];
    float*       out          = (float*)d_out;

    const int warps  = (N_ENT + NT - 1) / NT;      // 3636
    const int blocks = (warps + 7) / 8;            // 455
    dist_kernel<<<blocks, 256>>>(emb, all_emb, tail_r, source_idx,
                                 relation_ids, out);

    const int eblocks = (M_EDGES + 255) / 256;     // 1063
    edge_kernel<<<eblocks, 256>>>(heads, tails, edge_rels, out);
}